// round 5
// baseline (speedup 1.0000x reference)
#include <cuda_runtime.h>
#include <cstdint>

// OffsetPredictor: layer-1 (+bias) on mma.sync.m16n8k8.tf32 (fallback HMMA, plain sm_103),
// packed-f32x2 gelu + layer-2 epilogue. X(8,2048,256) f32 -> out (8,511,256,2) f32.
//
// Per warp: 16 channels (c..c+7, c+8..c+15) x 8 patches. M=channels(16), K=patch rows(8),
// N=hidden(64) -> 8 mma per patch, bias preloaded in accumulators.

#define B_DIM   8
#define L_DIM   2048
#define C_DIM   256
#define P_CNT   511
#define HID     64
#define NP      8
#define THREADS 128

// ---------- packed f32x2 helpers ----------
__device__ __forceinline__ uint64_t pk2(float lo, float hi) {
    uint64_t r; asm("mov.b64 %0, {%1, %2};" : "=l"(r) : "f"(lo), "f"(hi)); return r;
}
__device__ __forceinline__ void unpk2(uint64_t v, float& lo, float& hi) {
    asm("mov.b64 {%0, %1}, %2;" : "=f"(lo), "=f"(hi) : "l"(v));
}
__device__ __forceinline__ uint64_t fma2(uint64_t a, uint64_t b, uint64_t c) {
    uint64_t d; asm("fma.rn.f32x2 %0, %1, %2, %3;" : "=l"(d) : "l"(a), "l"(b), "l"(c)); return d;
}
__device__ __forceinline__ uint64_t mul2(uint64_t a, uint64_t b) {
    uint64_t d; asm("mul.rn.f32x2 %0, %1, %2;" : "=l"(d) : "l"(a), "l"(b)); return d;
}
__device__ __forceinline__ float tanha(float x) {
    float r; asm("tanh.approx.f32 %0, %1;" : "=f"(r) : "f"(x)); return r;
}
__device__ __forceinline__ uint32_t tf32r(float x) {
    uint32_t r; asm("cvt.rna.tf32.f32 %0, %1;" : "=r"(r) : "f"(x)); return r;
}

__device__ __forceinline__ void mma_tf32(float& c0, float& c1, float& c2, float& c3,
                                         uint32_t a0, uint32_t a1, uint32_t a2, uint32_t a3,
                                         uint32_t b0, uint32_t b1) {
    asm volatile("mma.sync.aligned.m16n8k8.row.col.f32.tf32.tf32.f32 "
        "{%0,%1,%2,%3}, {%4,%5,%6,%7}, {%8,%9}, {%0,%1,%2,%3};"
        : "+f"(c0), "+f"(c1), "+f"(c2), "+f"(c3)
        : "r"(a0), "r"(a1), "r"(a2), "r"(a3), "r"(b0), "r"(b1));
}

// gelu(x) = 0.5*x*(1 + tanh(x*R(x^2))); R fitted so tanh(x*R) ~ erf(x/sqrt(2)); err<=3e-5 |x|<=7
#define GT1 0.797884561f
#define GT3 0.0365411f
#define GT5 (-2.13723e-4f)
#define GT7 (-9.8600e-6f)

__device__ __forceinline__ uint64_t gelu2t(uint64_t x2, uint64_t T1, uint64_t T3,
                                           uint64_t T5, uint64_t T7, uint64_t HF) {
    uint64_t t2 = mul2(x2, x2);
    uint64_t r  = fma2(T7, t2, T5);
    r = fma2(r, t2, T3);
    r = fma2(r, t2, T1);
    uint64_t s2 = mul2(x2, r);
    float sl, sh; unpk2(s2, sl, sh);
    uint64_t tp = pk2(tanha(sl), tanha(sh));
    uint64_t ht = fma2(tp, HF, HF);
    return mul2(x2, ht);
}

__global__ __launch_bounds__(THREADS) void offset_predictor_mma(
    const float* __restrict__ X,
    const float* __restrict__ W1,   // (64, 8)
    const float* __restrict__ b1,   // (64,)
    const float* __restrict__ W2,   // (2, 64)
    const float* __restrict__ b2,   // (2,)
    float* __restrict__ out)        // (8, 511, 256, 2)
{
    __shared__ float      sB1[HID];
    __shared__ ulonglong2 sW2i[HID / 2];  // [j/2] = {pk(W2[0][j],W2[0][j+1]), pk(W2[1][j],W2[1][j+1])}
    __shared__ float      sB2[2];

    const int tid = threadIdx.x;
    if (tid < HID) sB1[tid] = b1[tid];
    if (tid < HID / 2) {
        const int j0 = 2 * tid;
        sW2i[tid].x = pk2(W2[j0],       W2[j0 + 1]);
        sW2i[tid].y = pk2(W2[HID + j0], W2[HID + j0 + 1]);
    }
    if (tid < 2) sB2[tid] = b2[tid];
    __syncthreads();

    const int lane = tid & 31;
    const int warp = tid >> 5;
    const int g    = lane >> 2;     // 0..7
    const int t    = lane & 3;      // 0..3
    const int b    = blockIdx.z;
    const int c    = blockIdx.y * 64 + warp * 16 + g;   // rowgroup A channel; rowgroup B = c+8
    const int p0   = blockIdx.x * NP;

    // W1 B-fragments, kept in registers for the whole kernel:
    // B[k][n] = W1[n][k]; thread owns (k=t, n=nt*8+g) and (k=t+4, n=nt*8+g)
    uint32_t bf0[8], bf1[8];
    #pragma unroll
    for (int nt = 0; nt < 8; nt++) {
        const int j = nt * 8 + g;
        bf0[nt] = tf32r(W1[j * 8 + t]);
        bf1[nt] = tf32r(W1[j * 8 + t + 4]);
    }

    const float b20 = sB2[0], b21 = sB2[1];
    const uint64_t T1 = pk2(GT1, GT1), T3 = pk2(GT3, GT3),
                   T5 = pk2(GT5, GT5), T7 = pk2(GT7, GT7), HF = pk2(0.5f, 0.5f);

    const float* Xb = X + (size_t)b * (L_DIM * C_DIM);

    // A fragments for patch p: a0 = X[4p+t][c], a1 = X[4p+t][c+8],
    //                          a2 = X[4p+t+4][c], a3 = X[4p+t+4][c+8]
    // (rows always < 2048 for p <= 510; shift trick: a2,a3 -> next patch's a0,a1)
    uint32_t a0 = tf32r(Xb[(size_t)(4 * p0 + t) * C_DIM + c]);
    uint32_t a1 = tf32r(Xb[(size_t)(4 * p0 + t) * C_DIM + c + 8]);
    uint32_t a2 = tf32r(Xb[(size_t)(4 * p0 + t + 4) * C_DIM + c]);
    uint32_t a3 = tf32r(Xb[(size_t)(4 * p0 + t + 4) * C_DIM + c + 8]);

    #pragma unroll 1
    for (int it = 0; it < NP; it++) {
        const int p = p0 + it;
        if (p >= P_CNT) break;          // uniform across block
        if (it > 0) {
            a0 = a2; a1 = a3;
            a2 = tf32r(Xb[(size_t)(4 * p + t + 4) * C_DIM + c]);
            a3 = tf32r(Xb[(size_t)(4 * p + t + 4) * C_DIM + c + 8]);
        }

        uint64_t o0A = 0, o1A = 0, o0B = 0, o1B = 0;   // packed {0.f,0.f}

        #pragma unroll
        for (int half = 0; half < 2; half++) {
            float d[4][4];
            #pragma unroll
            for (int q = 0; q < 4; q++) {
                const int nt = half * 4 + q;
                // D cols are (2t, 2t+1) -> accumulators init with bias b1[nt*8+2t .. +1]
                const float2 bb = *(const float2*)&sB1[nt * 8 + 2 * t];
                d[q][0] = bb.x; d[q][1] = bb.y; d[q][2] = bb.x; d[q][3] = bb.y;
                mma_tf32(d[q][0], d[q][1], d[q][2], d[q][3],
                         a0, a1, a2, a3, bf0[nt], bf1[nt]);
            }
            #pragma unroll
            for (int q = 0; q < 4; q++) {
                const int nt = half * 4 + q;
                const ulonglong2 w2 = sW2i[nt * 4 + t];   // j pair (nt*8+2t, +1)
                const uint64_t gA = gelu2t(pk2(d[q][0], d[q][1]), T1, T3, T5, T7, HF);
                o0A = fma2(w2.x, gA, o0A);
                o1A = fma2(w2.y, gA, o1A);
                const uint64_t gB = gelu2t(pk2(d[q][2], d[q][3]), T1, T3, T5, T7, HF);
                o0B = fma2(w2.x, gB, o0B);
                o1B = fma2(w2.y, gB, o1B);
            }
        }

        // horizontal sum of packed lanes, then butterfly over the 4 t-lanes
        float e0, e1;
        unpk2(o0A, e0, e1); float sA0 = e0 + e1;
        unpk2(o1A, e0, e1); float sA1 = e0 + e1;
        unpk2(o0B, e0, e1); float sB0 = e0 + e1;
        unpk2(o1B, e0, e1); float sB1v = e0 + e1;
        #pragma unroll
        for (int m = 1; m <= 2; m <<= 1) {
            sA0  += __shfl_xor_sync(0xffffffffu, sA0,  m);
            sA1  += __shfl_xor_sync(0xffffffffu, sA1,  m);
            sB0  += __shfl_xor_sync(0xffffffffu, sB0,  m);
            sB1v += __shfl_xor_sync(0xffffffffu, sB1v, m);
        }

        if (t == 0) {
            float2* opA = (float2*)(out + ((size_t)(b * P_CNT + p) * C_DIM + c) * 2);
            *opA = make_float2(sA0 + b20, sA1 + b21);
            float2* opB = (float2*)(out + ((size_t)(b * P_CNT + p) * C_DIM + c + 8) * 2);
            *opB = make_float2(sB0 + b20, sB1v + b21);
        }
    }
}

extern "C" void kernel_launch(void* const* d_in, const int* in_sizes, int n_in,
                              void* d_out, int out_size) {
    const float* X  = (const float*)d_in[0];
    const float* W1 = (const float*)d_in[1];
    const float* b1 = (const float*)d_in[2];
    const float* W2 = (const float*)d_in[3];
    const float* b2 = (const float*)d_in[4];
    float* out = (float*)d_out;

    dim3 grid((P_CNT + NP - 1) / NP, 4, B_DIM);   // (64, 4, 8)
    offset_predictor_mma<<<grid, THREADS>>>(X, W1, b1, W2, b2, out);
}

// round 9
// speedup vs baseline: 1.5226x; 1.5226x over previous
#include <cuda_runtime.h>
#include <cstdint>

// OffsetPredictor: BOTH layers on mma.sync.m16n8k8.tf32; gelu (tanh.approx) between,
// in D-fragment layout, no shuffles. X(8,2048,256) f32 -> out (8,511,256,2) f32.
//
// Per warp: 16 channels (g, g+8 rowgroups) x 1 patch per iteration, NP=8 patches.
// mma1: M=16 ch, K=8 patch rows, N=64 hidden (8 n-tiles), bias in accumulator init.
// mma2: M=16 ch, K=64 hidden (8 k-steps), N=8 (cols 0,1 = outputs, rest zero-weights),
//       A2 fragment == gelu(D1 fragment) under k-permutation folded into B2 weights.

#define B_DIM   8
#define L_DIM   2048
#define C_DIM   256
#define P_CNT   511
#define HID     64
#define NP      8
#define THREADS 128

__device__ __forceinline__ uint64_t pk2(float lo, float hi) {
    uint64_t r; asm("mov.b64 %0, {%1, %2};" : "=l"(r) : "f"(lo), "f"(hi)); return r;
}
__device__ __forceinline__ void unpk2(uint64_t v, float& lo, float& hi) {
    asm("mov.b64 {%0, %1}, %2;" : "=f"(lo), "=f"(hi) : "l"(v));
}
__device__ __forceinline__ uint64_t fma2(uint64_t a, uint64_t b, uint64_t c) {
    uint64_t d; asm("fma.rn.f32x2 %0, %1, %2, %3;" : "=l"(d) : "l"(a), "l"(b), "l"(c)); return d;
}
__device__ __forceinline__ uint64_t mul2(uint64_t a, uint64_t b) {
    uint64_t d; asm("mul.rn.f32x2 %0, %1, %2;" : "=l"(d) : "l"(a), "l"(b)); return d;
}
__device__ __forceinline__ float tanha(float x) {
    float r; asm("tanh.approx.f32 %0, %1;" : "=f"(r) : "f"(x)); return r;
}
__device__ __forceinline__ uint32_t tf32r(float x) {
    uint32_t r; asm("cvt.rna.tf32.f32 %0, %1;" : "=r"(r) : "f"(x)); return r;
}

__device__ __forceinline__ void mma_tf32(float& c0, float& c1, float& c2, float& c3,
                                         uint32_t a0, uint32_t a1, uint32_t a2, uint32_t a3,
                                         uint32_t b0, uint32_t b1) {
    asm volatile("mma.sync.aligned.m16n8k8.row.col.f32.tf32.tf32.f32 "
        "{%0,%1,%2,%3}, {%4,%5,%6,%7}, {%8,%9}, {%0,%1,%2,%3};"
        : "+f"(c0), "+f"(c1), "+f"(c2), "+f"(c3)
        : "r"(a0), "r"(a1), "r"(a2), "r"(a3), "r"(b0), "r"(b1));
}

// y = x + x*tanh(x*R(x^2));  (W2 prescaled by 0.5 makes this gelu*2 -> exact)
// R fitted so tanh(x*R(x^2)) ~ erf(x/sqrt(2)); |gelu err| <= ~3e-5 for |x| <= 7.
#define GT1 0.797884561f
#define GT3 0.0365411f
#define GT5 (-2.13723e-4f)
#define GT7 (-9.8600e-6f)

__device__ __forceinline__ uint64_t gelu2y(uint64_t x2, uint64_t T1, uint64_t T3,
                                           uint64_t T5, uint64_t T7) {
    uint64_t t2 = mul2(x2, x2);
    uint64_t r  = fma2(T7, t2, T5);
    r = fma2(r, t2, T3);
    r = fma2(r, t2, T1);
    uint64_t s2 = mul2(x2, r);
    float sl, sh; unpk2(s2, sl, sh);
    uint64_t tp = pk2(tanha(sl), tanha(sh));
    return fma2(x2, tp, x2);           // x*(1 + tanh(s))
}

__global__ __launch_bounds__(THREADS) void offset_predictor_mma2(
    const float* __restrict__ X,
    const float* __restrict__ W1,   // (64, 8)
    const float* __restrict__ b1,   // (64,)
    const float* __restrict__ W2,   // (2, 64)
    const float* __restrict__ b2,   // (2,)
    float* __restrict__ out)        // (8, 511, 256, 2)
{
    __shared__ float sB1[HID];
    const int tid = threadIdx.x;
    if (tid < HID) sB1[tid] = b1[tid];
    __syncthreads();

    const int lane = tid & 31;
    const int warp = tid >> 5;
    const int g    = lane >> 2;     // 0..7
    const int t    = lane & 3;      // 0..3
    const int b    = blockIdx.z;
    const int c    = blockIdx.y * 64 + warp * 16 + g;   // rowgroup A; rowgroup B = c+8
    const int p0   = blockIdx.x * NP;

    // mma1 B fragments (hidden n-tile nt): b0 = W1[nt*8+g][t], b1 = W1[nt*8+g][t+4]
    uint32_t bf0[8], bf1[8];
    #pragma unroll
    for (int nt = 0; nt < 8; nt++) {
        const int j = nt * 8 + g;
        bf0[nt] = tf32r(W1[j * 8 + t]);
        bf1[nt] = tf32r(W1[j * 8 + t + 4]);
    }

    // mma2 B fragments (k-step kt): k=t holds hidden col 2t of tile kt, k=t+4 holds col 2t+1.
    // Only n=g<2 columns carry W2 (prescaled by 0.5); rest are zero.
    uint32_t c2f0[8], c2f1[8];
    #pragma unroll
    for (int kt = 0; kt < 8; kt++) {
        const int j0 = kt * 8 + 2 * t;
        const float w0 = (g < 2) ? 0.5f * W2[g * HID + j0]     : 0.0f;
        const float w1 = (g < 2) ? 0.5f * W2[g * HID + j0 + 1] : 0.0f;
        c2f0[kt] = tf32r(w0);
        c2f1[kt] = tf32r(w1);
    }

    const float bias20 = b2[0], bias21 = b2[1];
    const uint64_t T1 = pk2(GT1, GT1), T3 = pk2(GT3, GT3),
                   T5 = pk2(GT5, GT5), T7 = pk2(GT7, GT7);

    const float* Xb = X + (size_t)b * (L_DIM * C_DIM);

    // A fragments for patch p: a0 = X[4p+t][c], a1 = X[4p+t][c+8],
    //                          a2 = X[4p+t+4][c], a3 = X[4p+t+4][c+8]
    uint32_t a0 = tf32r(Xb[(size_t)(4 * p0 + t) * C_DIM + c]);
    uint32_t a1 = tf32r(Xb[(size_t)(4 * p0 + t) * C_DIM + c + 8]);
    uint32_t a2 = tf32r(Xb[(size_t)(4 * p0 + t + 4) * C_DIM + c]);
    uint32_t a3 = tf32r(Xb[(size_t)(4 * p0 + t + 4) * C_DIM + c + 8]);

    #pragma unroll 1
    for (int it = 0; it < NP; it++) {
        const int p = p0 + it;
        if (p >= P_CNT) break;          // uniform across block
        if (it > 0) {
            a0 = a2; a1 = a3;
            a2 = tf32r(Xb[(size_t)(4 * p + t + 4) * C_DIM + c]);
            a3 = tf32r(Xb[(size_t)(4 * p + t + 4) * C_DIM + c + 8]);
        }

        // out accumulators (D2): lanes t==0 own cols 0,1 = the two outputs
        float e0 = (t == 0) ? bias20 : 0.0f;
        float e1 = (t == 0) ? bias21 : 0.0f;
        float e2 = e0, e3 = e1;

        #pragma unroll
        for (int nt = 0; nt < 8; nt++) {
            // layer-1: D cols (2t, 2t+1) -> bias init b1[nt*8+2t .. +1]
            const float2 bb = *(const float2*)&sB1[nt * 8 + 2 * t];
            float d0 = bb.x, d1 = bb.y, d2 = bb.x, d3 = bb.y;
            mma_tf32(d0, d1, d2, d3, a0, a1, a2, a3, bf0[nt], bf1[nt]);

            // gelu*2 in D layout: rows g (d0,d1), rows g+8 (d2,d3)
            const uint64_t yA = gelu2y(pk2(d0, d1), T1, T3, T5, T7);
            const uint64_t yB = gelu2y(pk2(d2, d3), T1, T3, T5, T7);
            float g0, g1, g2, g3;
            unpk2(yA, g0, g1);          // G[g][2t], G[g][2t+1]
            unpk2(yB, g2, g3);          // G[g+8][2t], G[g+8][2t+1]

            // layer-2 mma: A2 frag = {A2[g][t], A2[g+8][t], A2[g][t+4], A2[g+8][t+4]}
            //            = {G[g][2t], G[g+8][2t], G[g][2t+1], G[g+8][2t+1]}
            mma_tf32(e0, e1, e2, e3,
                     tf32r(g0), tf32r(g2), tf32r(g1), tf32r(g3),
                     c2f0[nt], c2f1[nt]);
        }

        if (t == 0) {
            float2* opA = (float2*)(out + ((size_t)(b * P_CNT + p) * C_DIM + c) * 2);
            *opA = make_float2(e0, e1);
            float2* opB = (float2*)(out + ((size_t)(b * P_CNT + p) * C_DIM + c + 8) * 2);
            *opB = make_float2(e2, e3);
        }
    }
}

extern "C" void kernel_launch(void* const* d_in, const int* in_sizes, int n_in,
                              void* d_out, int out_size) {
    const float* X  = (const float*)d_in[0];
    const float* W1 = (const float*)d_in[1];
    const float* b1 = (const float*)d_in[2];
    const float* W2 = (const float*)d_in[3];
    const float* b2 = (const float*)d_in[4];
    float* out = (float*)d_out;

    dim3 grid((P_CNT + NP - 1) / NP, 4, B_DIM);   // (64, 4, 8)
    offset_predictor_mma2<<<grid, THREADS>>>(X, W1, b1, W2, b2, out);
}

// round 10
// speedup vs baseline: 1.7456x; 1.1464x over previous
#include <cuda_runtime.h>
#include <cstdint>

// OffsetPredictor: BOTH layers on mma.sync.m16n8k8.tf32; gelu (tanh.approx) between,
// in D-fragment layout, no shuffles. X(8,2048,256) f32 -> out (8,511,256,2) f32.
//
// Per warp: 16 channels (g, g+8 rowgroups) x NP patches.
// mma1: M=16 ch, K=8 patch rows, N=64 hidden (8 n-tiles), bias in accumulator init.
// mma2: M=16 ch, K=64 hidden (8 k-steps), N=8 (cols 0,1 = outputs, rest zero-weights),
//       A2 fragment == gelu(D1 fragment) under k-permutation folded into B2 weights.
// Gelu outputs are fed to mma2 as RAW fp32 bits (HW tf32 truncation) - no cvt.

#define B_DIM   8
#define L_DIM   2048
#define C_DIM   256
#define P_CNT   511
#define HID     64
#define NP      8
#define THREADS 128

__device__ __forceinline__ uint64_t pk2(float lo, float hi) {
    uint64_t r; asm("mov.b64 %0, {%1, %2};" : "=l"(r) : "f"(lo), "f"(hi)); return r;
}
__device__ __forceinline__ void unpk2(uint64_t v, float& lo, float& hi) {
    asm("mov.b64 {%0, %1}, %2;" : "=f"(lo), "=f"(hi) : "l"(v));
}
__device__ __forceinline__ uint64_t fma2(uint64_t a, uint64_t b, uint64_t c) {
    uint64_t d; asm("fma.rn.f32x2 %0, %1, %2, %3;" : "=l"(d) : "l"(a), "l"(b), "l"(c)); return d;
}
__device__ __forceinline__ uint64_t mul2(uint64_t a, uint64_t b) {
    uint64_t d; asm("mul.rn.f32x2 %0, %1, %2;" : "=l"(d) : "l"(a), "l"(b)); return d;
}
__device__ __forceinline__ float tanha(float x) {
    float r; asm("tanh.approx.f32 %0, %1;" : "=f"(r) : "f"(x)); return r;
}
__device__ __forceinline__ uint32_t tf32r(float x) {
    uint32_t r; asm("cvt.rna.tf32.f32 %0, %1;" : "=r"(r) : "f"(x)); return r;
}

__device__ __forceinline__ void mma_tf32(float& c0, float& c1, float& c2, float& c3,
                                         uint32_t a0, uint32_t a1, uint32_t a2, uint32_t a3,
                                         uint32_t b0, uint32_t b1) {
    asm volatile("mma.sync.aligned.m16n8k8.row.col.f32.tf32.tf32.f32 "
        "{%0,%1,%2,%3}, {%4,%5,%6,%7}, {%8,%9}, {%0,%1,%2,%3};"
        : "+f"(c0), "+f"(c1), "+f"(c2), "+f"(c3)
        : "r"(a0), "r"(a1), "r"(a2), "r"(a3), "r"(b0), "r"(b1));
}

// y = x + x*tanh(x*R(x^2));  (W2 prescaled by 0.5 makes this 2*gelu -> exact)
// 3-term R(t) = GT1 + GT3*t + GT5*t^2 fitted so tanh(x*R(x^2)) ~ erf(x/sqrt(2));
// weighted gelu abs err <= ~6e-5 for |x| <= 7; saturation sign-safe to |x| ~ 13.
#define GT1 0.79788456f
#define GT3 0.036497f
#define GT5 (-2.367e-4f)

__device__ __forceinline__ uint64_t gelu2y(uint64_t x2, uint64_t T1, uint64_t T3,
                                           uint64_t T5) {
    uint64_t t2 = mul2(x2, x2);
    uint64_t r  = fma2(T5, t2, T3);
    r = fma2(r, t2, T1);
    uint64_t s2 = mul2(x2, r);
    float sl, sh; unpk2(s2, sl, sh);
    uint64_t tp = pk2(tanha(sl), tanha(sh));
    return fma2(x2, tp, x2);           // x*(1 + tanh(s))
}

__global__ __launch_bounds__(THREADS, 8) void offset_predictor_mma2(
    const float* __restrict__ X,
    const float* __restrict__ W1,   // (64, 8)
    const float* __restrict__ b1,   // (64,)
    const float* __restrict__ W2,   // (2, 64)
    const float* __restrict__ b2,   // (2,)
    float* __restrict__ out)        // (8, 511, 256, 2)
{
    __shared__ float sB1[HID];
    const int tid = threadIdx.x;
    if (tid < HID) sB1[tid] = b1[tid];
    __syncthreads();

    const int lane = tid & 31;
    const int warp = tid >> 5;
    const int g    = lane >> 2;     // 0..7
    const int t    = lane & 3;      // 0..3
    const int b    = blockIdx.z;
    const int c    = blockIdx.y * 64 + warp * 16 + g;   // rowgroup A; rowgroup B = c+8
    const int p0   = blockIdx.x * NP;

    // mma1 B fragments (hidden n-tile nt): b0 = W1[nt*8+g][t], b1 = W1[nt*8+g][t+4]
    uint32_t bf0[8], bf1[8];
    #pragma unroll
    for (int nt = 0; nt < 8; nt++) {
        const int j = nt * 8 + g;
        bf0[nt] = tf32r(W1[j * 8 + t]);
        bf1[nt] = tf32r(W1[j * 8 + t + 4]);
    }

    // mma2 B fragments (k-step kt): k=t holds hidden col 2t of tile kt, k=t+4 holds col 2t+1.
    // Only n=g<2 columns carry W2 (prescaled by 0.5); rest are zero.
    uint32_t c2f0[8], c2f1[8];
    #pragma unroll
    for (int kt = 0; kt < 8; kt++) {
        const int j0 = kt * 8 + 2 * t;
        const float w0 = (g < 2) ? 0.5f * W2[g * HID + j0]     : 0.0f;
        const float w1 = (g < 2) ? 0.5f * W2[g * HID + j0 + 1] : 0.0f;
        c2f0[kt] = tf32r(w0);
        c2f1[kt] = tf32r(w1);
    }

    const float bias20 = b2[0], bias21 = b2[1];
    const uint64_t T1 = pk2(GT1, GT1), T3 = pk2(GT3, GT3), T5 = pk2(GT5, GT5);

    const float* Xb = X + (size_t)b * (L_DIM * C_DIM);

    // A fragments for patch p: a0 = X[4p+t][c], a1 = X[4p+t][c+8],
    //                          a2 = X[4p+t+4][c], a3 = X[4p+t+4][c+8]
    uint32_t a0 = tf32r(Xb[(size_t)(4 * p0 + t) * C_DIM + c]);
    uint32_t a1 = tf32r(Xb[(size_t)(4 * p0 + t) * C_DIM + c + 8]);
    uint32_t a2 = tf32r(Xb[(size_t)(4 * p0 + t + 4) * C_DIM + c]);
    uint32_t a3 = tf32r(Xb[(size_t)(4 * p0 + t + 4) * C_DIM + c + 8]);

    #pragma unroll 1
    for (int it = 0; it < NP; it++) {
        const int p = p0 + it;
        if (p >= P_CNT) break;          // uniform across block
        if (it > 0) {
            a0 = a2; a1 = a3;
            a2 = tf32r(Xb[(size_t)(4 * p + t + 4) * C_DIM + c]);
            a3 = tf32r(Xb[(size_t)(4 * p + t + 4) * C_DIM + c + 8]);
        }

        // out accumulators (D2): lanes t==0 own cols 0,1 = the two outputs
        float e0 = (t == 0) ? bias20 : 0.0f;
        float e1 = (t == 0) ? bias21 : 0.0f;
        float e2 = e0, e3 = e1;

        #pragma unroll
        for (int nt = 0; nt < 8; nt++) {
            // layer-1: D cols (2t, 2t+1) -> bias init b1[nt*8+2t .. +1]
            const float2 bb = *(const float2*)&sB1[nt * 8 + 2 * t];
            float d0 = bb.x, d1 = bb.y, d2 = bb.x, d3 = bb.y;
            mma_tf32(d0, d1, d2, d3, a0, a1, a2, a3, bf0[nt], bf1[nt]);

            // 2*gelu in D layout: rows g (d0,d1), rows g+8 (d2,d3)
            const uint64_t yA = gelu2y(pk2(d0, d1), T1, T3, T5);
            const uint64_t yB = gelu2y(pk2(d2, d3), T1, T3, T5);
            float g0, g1, g2, g3;
            unpk2(yA, g0, g1);          // G[g][2t], G[g][2t+1]
            unpk2(yB, g2, g3);          // G[g+8][2t], G[g+8][2t+1]

            // layer-2 mma: A2 frag = {G[g][2t], G[g+8][2t], G[g][2t+1], G[g+8][2t+1]}
            // raw fp32 bits -> HW tf32 truncation (no cvt)
            mma_tf32(e0, e1, e2, e3,
                     __float_as_uint(g0), __float_as_uint(g2),
                     __float_as_uint(g1), __float_as_uint(g3),
                     c2f0[nt], c2f1[nt]);
        }

        if (t == 0) {
            float2* opA = (float2*)(out + ((size_t)(b * P_CNT + p) * C_DIM + c) * 2);
            *opA = make_float2(e0, e1);
            float2* opB = (float2*)(out + ((size_t)(b * P_CNT + p) * C_DIM + c + 8) * 2);
            *opB = make_float2(e2, e3);
        }
    }
}

extern "C" void kernel_launch(void* const* d_in, const int* in_sizes, int n_in,
                              void* d_out, int out_size) {
    const float* X  = (const float*)d_in[0];
    const float* W1 = (const float*)d_in[1];
    const float* b1 = (const float*)d_in[2];
    const float* W2 = (const float*)d_in[3];
    const float* b2 = (const float*)d_in[4];
    float* out = (float*)d_out;

    dim3 grid((P_CNT + NP - 1) / NP, 4, B_DIM);   // (64, 4, 8)
    offset_predictor_mma2<<<grid, THREADS>>>(X, W1, b1, W2, b2, out);
}